// round 9
// baseline (speedup 1.0000x reference)
#include <cuda_runtime.h>
#include <cuda_fp16.h>
#include <stdint.h>

#define B_   4
#define T_   256
#define U_   128
#define DE   512
#define DP   640
#define JD   1024
#define VO   1025

#define KC     64
#define NCHUNK 16
#define APITCH 72    // 64 + 8 pad (fp16 elems), pitch 144B
#define BPITCH 136   // 128 + 8 pad, pitch 272B

// ---- dynamic smem layout (bytes): 3-stage pipeline, M=256 tile ----
#define A_SZ   36864                     // half[256][72]
#define B_SZ   17408                     // half[64][136]
#define SM_A   0                         // 3 x A_SZ
#define SM_B   (3*A_SZ)                  // 3 x B_SZ
#define SM_TOTAL (SM_B + 3*B_SZ)         // 162816 bytes -> 1 CTA/SM
// epilogue staging reuses [0, 128*132*4 = 67584) ✓

// ---- device scratch ----
__device__ __align__(16) float g_enc_proj[B_*T_*JD];      // 4 MB
__device__ __align__(16) float g_pred_proj[B_*U_*JD];     // 2 MB
__device__ __align__(16) __half g_W16[JD*1024];           // [k][n] 2 MB
__device__ __align__(16) __half g_A16[(size_t)B_*T_*NCHUNK*U_*KC];  // 256 MB

// =====================================================================
// helpers
// =====================================================================
__device__ __forceinline__ uint32_t smem_u32(const void* p) {
    return (uint32_t)__cvta_generic_to_shared(p);
}
__device__ __forceinline__ void ldm_x4(uint32_t* r, uint32_t addr) {
    asm volatile("ldmatrix.sync.aligned.m8n8.x4.shared.b16 {%0,%1,%2,%3}, [%4];"
                 : "=r"(r[0]), "=r"(r[1]), "=r"(r[2]), "=r"(r[3]) : "r"(addr));
}
__device__ __forceinline__ void ldm_x4_t(uint32_t* r, uint32_t addr) {
    asm volatile("ldmatrix.sync.aligned.m8n8.x4.trans.shared.b16 {%0,%1,%2,%3}, [%4];"
                 : "=r"(r[0]), "=r"(r[1]), "=r"(r[2]), "=r"(r[3]) : "r"(addr));
}
__device__ __forceinline__ void mma16816(float* c, const uint32_t* a, const uint32_t* b) {
    asm volatile(
        "mma.sync.aligned.m16n8k16.row.col.f32.f16.f16.f32 "
        "{%0,%1,%2,%3},{%4,%5,%6,%7},{%8,%9},{%0,%1,%2,%3};"
        : "+f"(c[0]), "+f"(c[1]), "+f"(c[2]), "+f"(c[3])
        : "r"(a[0]), "r"(a[1]), "r"(a[2]), "r"(a[3]), "r"(b[0]), "r"(b[1]));
}
__device__ __forceinline__ void cp16(void* dst_smem, const void* src) {
    uint32_t d = smem_u32(dst_smem);
    asm volatile("cp.async.cg.shared.global [%0], [%1], 16;\n" :: "r"(d), "l"(src) : "memory");
}
__device__ __forceinline__ void cp_commit() {
    asm volatile("cp.async.commit_group;\n" ::: "memory");
}
template <int N>
__device__ __forceinline__ void cp_wait() {
    asm volatile("cp.async.wait_group %0;\n" :: "n"(N) : "memory");
}

// =====================================================================
// kernel 1: fp32 projection GEMM  C[M,J] = A[M,K] @ W[K,J] + bias
// =====================================================================
__global__ void __launch_bounds__(256) proj_gemm(
    const float* __restrict__ A, const float* __restrict__ W,
    const float* __restrict__ bias, float* __restrict__ C,
    int M, int K, int J)
{
    __shared__ float As[16][68];
    __shared__ float Bs[16][64];
    const int tx = threadIdx.x & 15;
    const int ty = threadIdx.x >> 4;
    const int m0 = blockIdx.y * 64;
    const int n0 = blockIdx.x * 64;

    float acc[4][4] = {};

    for (int k0 = 0; k0 < K; k0 += 16) {
        {
            int t = threadIdx.x;
            int m  = t >> 2, k4 = (t & 3) * 4;
            float4 a = *(const float4*)(A + (size_t)(m0 + m) * K + k0 + k4);
            As[k4 + 0][m] = a.x; As[k4 + 1][m] = a.y;
            As[k4 + 2][m] = a.z; As[k4 + 3][m] = a.w;
            int kk = t >> 4, n4 = (t & 15) * 4;
            *(float4*)&Bs[kk][n4] = *(const float4*)(W + (size_t)(k0 + kk) * J + n0 + n4);
        }
        __syncthreads();
        #pragma unroll
        for (int k = 0; k < 16; k++) {
            float a[4], b[4];
            *(float4*)a = *(float4*)&As[k][ty * 4];
            *(float4*)b = *(float4*)&Bs[k][tx * 4];
            #pragma unroll
            for (int i = 0; i < 4; i++)
                #pragma unroll
                for (int j = 0; j < 4; j++)
                    acc[i][j] += a[i] * b[j];
        }
        __syncthreads();
    }
    #pragma unroll
    for (int i = 0; i < 4; i++) {
        int m = m0 + ty * 4 + i;
        #pragma unroll
        for (int j = 0; j < 4; j++) {
            int n = n0 + tx * 4 + j;
            C[(size_t)m * J + n] = acc[i][j] + bias[n];
        }
    }
}

// =====================================================================
// kernel 2: W_out[:, 0:1024] -> fp16 [k][n]
// =====================================================================
__global__ void prep_w(const float* __restrict__ W) {
    int idx = blockIdx.x * 256 + threadIdx.x;
    if (idx >= JD * 1024) return;
    int j = idx >> 10, n = idx & 1023;
    g_W16[idx] = __float2half_rn(W[(size_t)j * VO + n]);
}

// =====================================================================
// kernel 3: precompute fp16 joint activations + blank column
// =====================================================================
__global__ void __launch_bounds__(256) precompute_A(
    const float* __restrict__ Wout, const float* __restrict__ bout,
    float* __restrict__ out)
{
    __shared__ float enc_s[JD];
    __shared__ float wb_s[JD];
    const int bt   = blockIdx.x;
    const int b    = bt >> 8;
    const int t    = threadIdx.x;
    const int warp = t >> 5;
    const int lane = t & 31;
    const int g    = lane & 7;          // granule (8 fp16 = 16B)
    const int rsub = lane >> 3;         // 0..3 row-in-warp
    const int u0   = warp * 4 + rsub;   // + p*32

    ((float4*)enc_s)[t] = ((const float4*)(g_enc_proj + (size_t)bt * JD))[t];
    for (int i = t; i < JD; i += 256)
        wb_s[i] = Wout[(size_t)i * VO + (VO - 1)];
    __syncthreads();

    const float* pbase = g_pred_proj + ((size_t)(b * U_ + u0)) * JD;
    float accb[4] = {0.f, 0.f, 0.f, 0.f};

    #pragma unroll 2
    for (int c = 0; c < NCHUNK; c++) {
        const int j0 = c * KC + g * 8;
        float4 e0 = *(const float4*)(enc_s + j0);
        float4 e1 = *(const float4*)(enc_s + j0 + 4);
        float4 w0 = *(const float4*)(wb_s + j0);
        float4 w1 = *(const float4*)(wb_s + j0 + 4);
        __half* dstc = g_A16 + (((size_t)bt * NCHUNK + c) * U_ + u0) * KC + g * 8;
        #pragma unroll
        for (int p = 0; p < 4; p++) {
            const float* prow = pbase + (size_t)(p * 32) * JD + j0;
            float4 pa = *(const float4*)(prow);
            float4 pb = *(const float4*)(prow + 4);
            float h0 = fmaxf(pa.x + e0.x, 0.f);
            float h1 = fmaxf(pa.y + e0.y, 0.f);
            float h2 = fmaxf(pa.z + e0.z, 0.f);
            float h3 = fmaxf(pa.w + e0.w, 0.f);
            float h4 = fmaxf(pb.x + e1.x, 0.f);
            float h5 = fmaxf(pb.y + e1.y, 0.f);
            float h6 = fmaxf(pb.z + e1.z, 0.f);
            float h7 = fmaxf(pb.w + e1.w, 0.f);
            accb[p] += h0 * w0.x + h1 * w0.y + h2 * w0.z + h3 * w0.w
                     + h4 * w1.x + h5 * w1.y + h6 * w1.z + h7 * w1.w;
            __half2 v0 = __floats2half2_rn(h0, h1);
            __half2 v1 = __floats2half2_rn(h2, h3);
            __half2 v2 = __floats2half2_rn(h4, h5);
            __half2 v3 = __floats2half2_rn(h6, h7);
            *(uint4*)(dstc + (size_t)(p * 32) * KC) = make_uint4(
                *(uint32_t*)&v0, *(uint32_t*)&v1, *(uint32_t*)&v2, *(uint32_t*)&v3);
        }
    }

    const float bias_bl = bout[VO - 1];
    #pragma unroll
    for (int p = 0; p < 4; p++) {
        float a = accb[p];
        a += __shfl_xor_sync(0xffffffffu, a, 1);
        a += __shfl_xor_sync(0xffffffffu, a, 2);
        a += __shfl_xor_sync(0xffffffffu, a, 4);
        if (g == 0)
            out[((size_t)bt * U_ + u0 + p * 32) * VO + (VO - 1)] = a + bias_bl;
    }
}

// =====================================================================
// kernel 4: fused joint GEMM, CTA tile M=256 (2 bt) x N=128
// warps: 4(M) x 2(N), warp tile 64x64. 3-stage cp.async pipeline.
// =====================================================================
__global__ void __launch_bounds__(256, 1) joint_main(
    const float* __restrict__ bout, float* __restrict__ out)
{
    extern __shared__ char sm[];

    const int bt0   = blockIdx.y * 2;      // 2 bt per CTA
    const int ntile = blockIdx.x;          // 0..7
    const int n0    = ntile * 128;
    const int t     = threadIdx.x;
    const int warp  = t >> 5;
    const int lane  = t & 31;
    const int wm    = warp >> 1;           // 0..3 (M, 64 rows each)
    const int wn    = warp & 1;            // 0..1 (N, 64 cols each)
    const int lr    = lane & 15;
    const int lc    = (lane >> 4) * 8;

    const __half* Ab0 = g_A16 + (size_t)(bt0    ) * NCHUNK * U_ * KC;
    const __half* Ab1 = g_A16 + (size_t)(bt0 + 1) * NCHUNK * U_ * KC;

    auto issueAB = [&](int c, int buf) {
        // A: 256 rows x 64 fp16 (rows 0..127 from bt0, 128..255 from bt1)
        __half* adst = (__half*)(sm + SM_A + buf * A_SZ);
        const __half* a0 = Ab0 + (size_t)c * U_ * KC;
        const __half* a1 = Ab1 + (size_t)c * U_ * KC;
        #pragma unroll
        for (int i = 0; i < 8; i++) {
            int flat = t + 256 * i;                 // 0..2047
            int row = flat >> 3, g = flat & 7;      // 256 rows x 8 x 16B
            const __half* src = (i < 4) ? (a0 + row * KC + g * 8)
                                        : (a1 + (row - 128) * KC + g * 8);
            cp16(adst + row * APITCH + g * 8, src);
        }
        // B: 64 k-rows x 128 n fp16
        const __half* bsrc = g_W16 + (size_t)(c * KC) * 1024 + n0;
        __half* bdst = (__half*)(sm + SM_B + buf * B_SZ);
        #pragma unroll
        for (int i = 0; i < 4; i++) {
            int flat = t + 256 * i;                 // 0..1023
            int row = flat >> 4, c16 = flat & 15;   // 64 rows x 16 x 16B
            cp16(bdst + row * BPITCH + c16 * 8, bsrc + (size_t)row * 1024 + c16 * 8);
        }
        cp_commit();
    };

    float acc[4][8][4] = {};   // mt x nt x frag

    issueAB(0, 0);
    issueAB(1, 1);

    int buf = 0;
    for (int c = 0; c < NCHUNK; c++) {
        cp_wait<1>();
        __syncthreads();
        if (c + 2 < NCHUNK) {
            int nb = buf + 2; if (nb >= 3) nb -= 3;
            issueAB(c + 2, nb);
        }

        uint32_t aB = smem_u32(sm + SM_A + buf * A_SZ) + (uint32_t)(((wm * 64 + lr) * APITCH + lc) * 2);
        uint32_t bB = smem_u32(sm + SM_B + buf * B_SZ) + (uint32_t)((lr * BPITCH + wn * 64 + lc) * 2);

        #pragma unroll
        for (int ks = 0; ks < 4; ks++) {
            uint32_t bq[4][4];
            #pragma unroll
            for (int n2 = 0; n2 < 4; n2++)
                ldm_x4_t(bq[n2], bB + (uint32_t)((ks * 16 * BPITCH + n2 * 16) * 2));
            #pragma unroll
            for (int mt = 0; mt < 4; mt++) {
                uint32_t a[4];
                ldm_x4(a, aB + (uint32_t)((mt * 16 * APITCH + ks * 16) * 2));
                #pragma unroll
                for (int nt = 0; nt < 8; nt++) {
                    const uint32_t* bp = &bq[nt >> 1][(nt & 1) * 2];
                    mma16816(acc[mt][nt], a, bp);
                }
            }
        }
        if (++buf >= 3) buf = 0;
    }
    __syncthreads();   // protect staging region (aliases buffers)

    // ---- epilogue: two 128-row passes through smem staging ----
    float* stg = (float*)sm;               // 128 x 132 floats = 67584 B
    const int gid = lane >> 2, tig = lane & 3;

    float bo[4];
    #pragma unroll
    for (int i = 0; i < 4; i++) bo[i] = bout[n0 + i * 32 + lane];

    #pragma unroll
    for (int p = 0; p < 2; p++) {
        if ((warp >> 2) == p) {            // wm in {2p, 2p+1}
            const int wml = wm & 1;        // 0..1 within this pass
            #pragma unroll
            for (int mt = 0; mt < 4; mt++) {
                #pragma unroll
                for (int nt = 0; nt < 8; nt++) {
                    float* cv = acc[mt][nt];
                    int u0 = wml * 64 + mt * 16 + gid;
                    int c0 = wn * 64 + nt * 8 + tig * 2;
                    *(float2*)&stg[u0 * 132 + c0]       = make_float2(cv[0], cv[1]);
                    *(float2*)&stg[(u0 + 8) * 132 + c0] = make_float2(cv[2], cv[3]);
                }
            }
        }
        __syncthreads();
        float* obase = out + ((size_t)(bt0 + p) * U_) * VO + n0;
        #pragma unroll
        for (int ri = 0; ri < 16; ri++) {
            int row = warp * 16 + ri;
            float* orow = obase + (size_t)row * VO;
            #pragma unroll
            for (int i = 0; i < 4; i++)
                orow[i * 32 + lane] = stg[row * 132 + i * 32 + lane] + bo[i];
        }
        __syncthreads();
    }
}

// =====================================================================
extern "C" void kernel_launch(void* const* d_in, const int* in_sizes, int n_in,
                              void* d_out, int out_size)
{
    (void)in_sizes; (void)n_in; (void)out_size;
    const float* enc    = (const float*)d_in[0];
    const float* pred   = (const float*)d_in[1];
    const float* W_enc  = (const float*)d_in[2];
    const float* b_enc  = (const float*)d_in[3];
    const float* W_pred = (const float*)d_in[4];
    const float* b_pred = (const float*)d_in[5];
    const float* W_out  = (const float*)d_in[6];
    const float* b_out  = (const float*)d_in[7];
    float* out = (float*)d_out;

    void *pe, *pp;
    cudaGetSymbolAddress(&pe, g_enc_proj);
    cudaGetSymbolAddress(&pp, g_pred_proj);
    float* genc  = (float*)pe;
    float* gpred = (float*)pp;

    cudaFuncSetAttribute(joint_main, cudaFuncAttributeMaxDynamicSharedMemorySize, SM_TOTAL);

    dim3 pg1(JD / 64, (B_ * T_) / 64);
    proj_gemm<<<pg1, 256>>>(enc, W_enc, b_enc, genc, B_ * T_, DE, JD);
    dim3 pg2(JD / 64, (B_ * U_) / 64);
    proj_gemm<<<pg2, 256>>>(pred, W_pred, b_pred, gpred, B_ * U_, DP, JD);
    prep_w<<<(JD * 1024 + 255) / 256, 256>>>(W_out);
    precompute_A<<<B_ * T_, 256>>>(W_out, b_out, out);

    dim3 grid(8, (B_ * T_) / 2);         // 8 n-tiles x 512 M-tiles (M=256)
    joint_main<<<grid, 256, SM_TOTAL>>>(b_out, out);
}

// round 10
// speedup vs baseline: 1.0937x; 1.0937x over previous
#include <cuda_runtime.h>
#include <cuda_fp16.h>
#include <stdint.h>

#define B_   4
#define T_   256
#define U_   128
#define DE   512
#define DP   640
#define JD   1024
#define VO   1025

#define KC     64
#define NCHUNK 16

// ---- dynamic smem (joint): epilogue staging only ----
#define SM_TOTAL (128*132*4)             // 67584 -> 2 CTAs/SM

// ---- device scratch ----
__device__ __align__(16) float g_enc_proj[B_*T_*JD];      // 4 MB
__device__ __align__(16) float g_pred_proj[B_*U_*JD];     // 2 MB
// W fragments: uint2 [c(16)][n8(128)][kh(4)][lane(32)]   // 2 MB
__device__ __align__(16) uint2 g_Wfrag[NCHUNK*128*4*32];
// A fragments: uint4 [bt(1024)][c(16)][mh(8)][kh(4)][lane(32)]  // 256 MB
__device__ __align__(16) uint4 g_Afrag[(size_t)B_*T_*NCHUNK*8*4*32];

// =====================================================================
// helpers
// =====================================================================
__device__ __forceinline__ void mma16816(float* c, const uint32_t* a, const uint32_t* b) {
    asm volatile(
        "mma.sync.aligned.m16n8k16.row.col.f32.f16.f16.f32 "
        "{%0,%1,%2,%3},{%4,%5,%6,%7},{%8,%9},{%0,%1,%2,%3};"
        : "+f"(c[0]), "+f"(c[1]), "+f"(c[2]), "+f"(c[3])
        : "r"(a[0]), "r"(a[1]), "r"(a[2]), "r"(a[3]), "r"(b[0]), "r"(b[1]));
}

// =====================================================================
// kernel 1: fp32 projection GEMM  C[M,J] = A[M,K] @ W[K,J] + bias
// =====================================================================
__global__ void __launch_bounds__(256) proj_gemm(
    const float* __restrict__ A, const float* __restrict__ W,
    const float* __restrict__ bias, float* __restrict__ C,
    int M, int K, int J)
{
    __shared__ float As[16][68];
    __shared__ float Bs[16][64];
    const int tx = threadIdx.x & 15;
    const int ty = threadIdx.x >> 4;
    const int m0 = blockIdx.y * 64;
    const int n0 = blockIdx.x * 64;

    float acc[4][4] = {};

    for (int k0 = 0; k0 < K; k0 += 16) {
        {
            int t = threadIdx.x;
            int m  = t >> 2, k4 = (t & 3) * 4;
            float4 a = *(const float4*)(A + (size_t)(m0 + m) * K + k0 + k4);
            As[k4 + 0][m] = a.x; As[k4 + 1][m] = a.y;
            As[k4 + 2][m] = a.z; As[k4 + 3][m] = a.w;
            int kk = t >> 4, n4 = (t & 15) * 4;
            *(float4*)&Bs[kk][n4] = *(const float4*)(W + (size_t)(k0 + kk) * J + n0 + n4);
        }
        __syncthreads();
        #pragma unroll
        for (int k = 0; k < 16; k++) {
            float a[4], b[4];
            *(float4*)a = *(float4*)&As[k][ty * 4];
            *(float4*)b = *(float4*)&Bs[k][tx * 4];
            #pragma unroll
            for (int i = 0; i < 4; i++)
                #pragma unroll
                for (int j = 0; j < 4; j++)
                    acc[i][j] += a[i] * b[j];
        }
        __syncthreads();
    }
    #pragma unroll
    for (int i = 0; i < 4; i++) {
        int m = m0 + ty * 4 + i;
        #pragma unroll
        for (int j = 0; j < 4; j++) {
            int n = n0 + tx * 4 + j;
            C[(size_t)m * J + n] = acc[i][j] + bias[n];
        }
    }
}

// =====================================================================
// kernel 2: W_out[:, 0:1024] -> fp16 B-fragments (col-major n8k16)
// idx = ((c*128 + n8)*4 + kh)*32 + lane
// b0 = (k0, n),(k0+1, n)  b1 = (k0+8, n),(k0+9, n); k0=(lane&3)*2, n=n8*8+lane/4
// =====================================================================
__global__ void __launch_bounds__(256) prep_w(const float* __restrict__ W) {
    int idx = blockIdx.x * 256 + threadIdx.x;     // 0..262143
    int lane = idx & 31;
    int kh   = (idx >> 5) & 3;
    int n8   = (idx >> 7) & 127;
    int c    = idx >> 14;
    int j = c * 64 + kh * 16 + (lane & 3) * 2;
    int n = n8 * 8 + (lane >> 2);
    __half2 b0 = __floats2half2_rn(W[(size_t)j * VO + n], W[(size_t)(j + 1) * VO + n]);
    __half2 b1 = __floats2half2_rn(W[(size_t)(j + 8) * VO + n], W[(size_t)(j + 9) * VO + n]);
    g_Wfrag[idx] = make_uint2(*(uint32_t*)&b0, *(uint32_t*)&b1);
}

// =====================================================================
// kernel 3: precompute fp16 joint activations as A-fragments + blank column
// warp w = m16-block mh; thread: rows r=w*16+lane/4 and r+8,
// cols (lane&3)*2 (+1,+8,+9) within each k16 block.
// =====================================================================
__global__ void __launch_bounds__(256) precompute_A(
    const float* __restrict__ Wout, const float* __restrict__ bout,
    float* __restrict__ out)
{
    __shared__ float enc_s[JD];
    __shared__ float wb_s[JD];
    const int bt   = blockIdx.x;
    const int b    = bt >> 8;
    const int t    = threadIdx.x;
    const int w    = t >> 5;
    const int lane = t & 31;
    const int r    = w * 16 + (lane >> 2);
    const int cl   = (lane & 3) * 2;

    ((float4*)enc_s)[t] = ((const float4*)(g_enc_proj + (size_t)bt * JD))[t];
    for (int i = t; i < JD; i += 256)
        wb_s[i] = Wout[(size_t)i * VO + (VO - 1)];
    __syncthreads();

    const float* pr0 = g_pred_proj + ((size_t)(b * U_ + r)) * JD;
    const float* pr1 = pr0 + 8 * JD;
    uint4* aOut = g_Afrag + (((size_t)bt * NCHUNK) * 8 + w) * 4 * 32 + lane;
    float accR = 0.f, accR8 = 0.f;

    #pragma unroll 2
    for (int c = 0; c < NCHUNK; c++) {
        #pragma unroll
        for (int kh = 0; kh < 4; kh++) {
            const int j = c * 64 + kh * 16 + cl;
            float2 e0 = *(const float2*)&enc_s[j];
            float2 e1 = *(const float2*)&enc_s[j + 8];
            float2 w0 = *(const float2*)&wb_s[j];
            float2 w1 = *(const float2*)&wb_s[j + 8];
            float2 p00 = *(const float2*)&pr0[j];
            float2 p01 = *(const float2*)&pr0[j + 8];
            float2 p10 = *(const float2*)&pr1[j];
            float2 p11 = *(const float2*)&pr1[j + 8];
            float h00x = fmaxf(p00.x + e0.x, 0.f), h00y = fmaxf(p00.y + e0.y, 0.f);
            float h01x = fmaxf(p01.x + e1.x, 0.f), h01y = fmaxf(p01.y + e1.y, 0.f);
            float h10x = fmaxf(p10.x + e0.x, 0.f), h10y = fmaxf(p10.y + e0.y, 0.f);
            float h11x = fmaxf(p11.x + e1.x, 0.f), h11y = fmaxf(p11.y + e1.y, 0.f);
            accR  += h00x * w0.x + h00y * w0.y + h01x * w1.x + h01y * w1.y;
            accR8 += h10x * w0.x + h10y * w0.y + h11x * w1.x + h11y * w1.y;
            __half2 a0 = __floats2half2_rn(h00x, h00y);
            __half2 a1 = __floats2half2_rn(h10x, h10y);
            __half2 a2 = __floats2half2_rn(h01x, h01y);
            __half2 a3 = __floats2half2_rn(h11x, h11y);
            aOut[(size_t)(c * 8) * 4 * 32 + kh * 32] = make_uint4(
                *(uint32_t*)&a0, *(uint32_t*)&a1, *(uint32_t*)&a2, *(uint32_t*)&a3);
        }
    }

    accR  += __shfl_xor_sync(0xffffffffu, accR, 1);
    accR  += __shfl_xor_sync(0xffffffffu, accR, 2);
    accR8 += __shfl_xor_sync(0xffffffffu, accR8, 1);
    accR8 += __shfl_xor_sync(0xffffffffu, accR8, 2);
    if ((lane & 3) == 0) {
        const float bb = bout[VO - 1];
        out[((size_t)bt * U_ + r) * VO + (VO - 1)]     = accR  + bb;
        out[((size_t)bt * U_ + r + 8) * VO + (VO - 1)] = accR8 + bb;
    }
}

// =====================================================================
// kernel 4: joint GEMM — direct-LDG fragments, no smem in main loop
// CTA 128x128 (bt x n-tile), warps 2(M)x4(N), warp tile 64x32
// =====================================================================
__global__ void __launch_bounds__(256, 2) joint_main(
    const float* __restrict__ bout, float* __restrict__ out)
{
    extern __shared__ char sm[];

    const int bt    = blockIdx.y;          // 0..1023
    const int ntile = blockIdx.x;          // 0..7
    const int n0    = ntile * 128;
    const int t     = threadIdx.x;
    const int warp  = t >> 5;
    const int lane  = t & 31;
    const int wm    = warp >> 2;           // 0..1 (M)
    const int wn    = warp & 3;            // 0..3 (N)

    float acc[4][4][4] = {};

    // per-thread fragment pointers
    const uint4* aC = g_Afrag + (((size_t)bt * NCHUNK * 8) + wm * 4) * 128 + lane;
    const uint2* bC = g_Wfrag + (size_t)(ntile * 16 + wn * 4) * 128 + lane;

    for (int c = 0; c < NCHUNK; c++) {
        #pragma unroll
        for (int kh = 0; kh < 4; kh++) {
            uint2 bq[4];
            #pragma unroll
            for (int nt = 0; nt < 4; nt++)
                bq[nt] = bC[(size_t)c * 16384 + nt * 128 + kh * 32];
            #pragma unroll
            for (int mt = 0; mt < 4; mt++) {
                uint4 av = aC[(size_t)c * 1024 + mt * 128 + kh * 32];
                uint32_t a[4] = {av.x, av.y, av.z, av.w};
                #pragma unroll
                for (int nt = 0; nt < 4; nt++)
                    mma16816(acc[mt][nt], a, (const uint32_t*)&bq[nt]);
            }
        }
    }

    // ---- coalesced epilogue: stage f32 tile in smem, then contiguous STG ----
    float* stg = (float*)sm;               // 128 x 132 floats = 67584 B
    const int gid = lane >> 2, tig = lane & 3;
    #pragma unroll
    for (int mt = 0; mt < 4; mt++) {
        #pragma unroll
        for (int nt = 0; nt < 4; nt++) {
            float* cv = acc[mt][nt];
            int u0 = wm * 64 + mt * 16 + gid;
            int c0 = wn * 32 + nt * 8 + tig * 2;
            *(float2*)&stg[u0 * 132 + c0]       = make_float2(cv[0], cv[1]);
            *(float2*)&stg[(u0 + 8) * 132 + c0] = make_float2(cv[2], cv[3]);
        }
    }
    __syncthreads();

    float bo[4];
    #pragma unroll
    for (int i = 0; i < 4; i++) bo[i] = bout[n0 + i * 32 + lane];

    #pragma unroll
    for (int ri = 0; ri < 16; ri++) {
        int row = warp * 16 + ri;
        float* orow = out + ((size_t)bt * U_ + row) * VO + n0;
        #pragma unroll
        for (int i = 0; i < 4; i++)
            orow[i * 32 + lane] = stg[row * 132 + i * 32 + lane] + bo[i];
    }
}

// =====================================================================
extern "C" void kernel_launch(void* const* d_in, const int* in_sizes, int n_in,
                              void* d_out, int out_size)
{
    (void)in_sizes; (void)n_in; (void)out_size;
    const float* enc    = (const float*)d_in[0];
    const float* pred   = (const float*)d_in[1];
    const float* W_enc  = (const float*)d_in[2];
    const float* b_enc  = (const float*)d_in[3];
    const float* W_pred = (const float*)d_in[4];
    const float* b_pred = (const float*)d_in[5];
    const float* W_out  = (const float*)d_in[6];
    const float* b_out  = (const float*)d_in[7];
    float* out = (float*)d_out;

    void *pe, *pp;
    cudaGetSymbolAddress(&pe, g_enc_proj);
    cudaGetSymbolAddress(&pp, g_pred_proj);
    float* genc  = (float*)pe;
    float* gpred = (float*)pp;

    cudaFuncSetAttribute(joint_main, cudaFuncAttributeMaxDynamicSharedMemorySize, SM_TOTAL);

    dim3 pg1(JD / 64, (B_ * T_) / 64);
    proj_gemm<<<pg1, 256>>>(enc, W_enc, b_enc, genc, B_ * T_, DE, JD);
    dim3 pg2(JD / 64, (B_ * U_) / 64);
    proj_gemm<<<pg2, 256>>>(pred, W_pred, b_pred, gpred, B_ * U_, DP, JD);
    prep_w<<<1024, 256>>>(W_out);
    precompute_A<<<B_ * T_, 256>>>(W_out, b_out, out);

    dim3 grid(8, B_ * T_);               // 8 n-tiles x 1024 (b,t) tiles
    joint_main<<<grid, 256, SM_TOTAL>>>(b_out, out);
}